// round 1
// baseline (speedup 1.0000x reference)
#include <cuda_runtime.h>

// ---------------- problem constants ----------------
#define K_B 2
#define K_R 5
#define K_N 1024
#define K_E 3
#define K_F 64
#define K_INRET 320
#define K_INTER 256
#define K_OUTRET 256
#define K_H1 128
#define K_HRET 320
#define K_NCLS 2
#define K_CAT (K_OUTRET + K_H1)   // 384
#define INV_GAMMA 0.4f            // 1/2.5

// ---------------- device scratch (no runtime alloc allowed) ----------------
__device__ float g_S[K_R * K_N * K_N];                 // 20 MB
__device__ float g_feats[K_B * K_R * K_N * K_F];
__device__ float g_diff [K_B * K_R * K_N * K_F];
__device__ float g_h    [K_B * K_R * K_N * K_F];       // u / next h; also xr view [B,N,320]
__device__ float g_q [K_B * K_N * K_INTER];
__device__ float g_k [K_B * K_N * K_INTER];
__device__ float g_v [K_B * K_N * K_INTER];
__device__ float g_ms[K_B * K_N * K_N];                // masked scores, 8 MB
__device__ float g_ret[K_B * K_N * K_OUTRET];
__device__ float g_eta[K_B * K_N * K_OUTRET];
__device__ float g_ts [K_B * K_N * K_H1];
__device__ float g_cat[K_B * K_N * K_CAT];
__device__ float g_skipA[K_B * K_N * K_HRET];
__device__ float g_skipB[K_B * K_N * K_HRET];
__device__ float g_m1[K_B * K_N * K_H1];

// ---------------- S[r,n,m] = sum_e theta[l,r,e] * T[l,r,e,n,m] ----------------
__global__ void k_S(const float* __restrict__ T, const float* __restrict__ theta,
                    float* __restrict__ S, int l) {
    long i = (long)blockIdx.x * blockDim.x + threadIdx.x;
    const long total = (long)K_R * K_N * K_N / 4;
    if (i >= total) return;
    long e = i * 4;
    int r = (int)(e / ((long)K_N * K_N));
    long p = e - (long)r * K_N * K_N;
    const float* tb = T + ((long)(l * K_R + r) * K_E) * K_N * K_N + p;
    float t0 = theta[(l * K_R + r) * K_E + 0];
    float t1 = theta[(l * K_R + r) * K_E + 1];
    float t2 = theta[(l * K_R + r) * K_E + 2];
    float4 v0 = *(const float4*)(tb);
    float4 v1 = *(const float4*)(tb + (long)K_N * K_N);
    float4 v2 = *(const float4*)(tb + 2L * K_N * K_N);
    float4 o;
    o.x = t0 * v0.x + t1 * v1.x + t2 * v2.x;
    o.y = t0 * v0.y + t1 * v1.y + t2 * v2.y;
    o.z = t0 * v0.z + t1 * v1.z + t2 * v2.z;
    o.w = t0 * v0.w + t1 * v1.w + t2 * v2.w;
    *(float4*)(S + e) = o;
}

// ---------------- feats[b,r] = (S[r] .* a[b,r]) @ h[b,r]  (NN, A fused on the fly) ----
// grid: (1, N/64, B*R), block (16,16). Nc = F = 64, K = N.
__global__ void k_feats(const float* __restrict__ S, const float* __restrict__ Ab,
                        const float* __restrict__ H, float* __restrict__ out) {
    int z = blockIdx.z;
    int r = z % K_R;
    const float* Sz = S  + (long)r * K_N * K_N;
    const float* Az = Ab + (long)z * K_N * K_N;
    const float* Hz = H  + (long)z * K_N * K_F;
    float*       Cz = out + (long)z * K_N * K_F;
    int m0 = blockIdx.y * 64;
    __shared__ float As[64][17];
    __shared__ float Bs[16][68];
    int tx = threadIdx.x, ty = threadIdx.y;
    int tid = ty * 16 + tx;
    int lar = tid >> 2, lac = (tid & 3) << 2;
    int lbk = tid >> 4, lbn = (tid & 15) << 2;
    float acc[4][4] = {};
    for (int k0 = 0; k0 < K_N; k0 += 16) {
        float4 s4 = *(const float4*)(Sz + (long)(m0 + lar) * K_N + k0 + lac);
        float4 a4 = *(const float4*)(Az + (long)(m0 + lar) * K_N + k0 + lac);
        As[lar][lac + 0] = s4.x * a4.x;
        As[lar][lac + 1] = s4.y * a4.y;
        As[lar][lac + 2] = s4.z * a4.z;
        As[lar][lac + 3] = s4.w * a4.w;
        float4 h4 = *(const float4*)(Hz + (long)(k0 + lbk) * K_F + lbn);
        Bs[lbk][lbn + 0] = h4.x;
        Bs[lbk][lbn + 1] = h4.y;
        Bs[lbk][lbn + 2] = h4.z;
        Bs[lbk][lbn + 3] = h4.w;
        __syncthreads();
#pragma unroll
        for (int kk = 0; kk < 16; kk++) {
            float av[4], bv[4];
#pragma unroll
            for (int i = 0; i < 4; i++) { av[i] = As[ty * 4 + i][kk]; bv[i] = Bs[kk][tx * 4 + i]; }
#pragma unroll
            for (int i = 0; i < 4; i++)
#pragma unroll
                for (int j = 0; j < 4; j++) acc[i][j] += av[i] * bv[j];
        }
        __syncthreads();
    }
#pragma unroll
    for (int i = 0; i < 4; i++) {
        int row = m0 + ty * 4 + i;
#pragma unroll
        for (int j = 0; j < 4; j++) {
            int col = tx * 4 + j;
            Cz[(long)row * K_F + col] = acc[i][j];
        }
    }
}

// ---------------- generic NT GEMM: C = act( A @ W^T + bias ), optional D_gamma mask ----
// A: [M,K] row-major, W: [Nc,K] row-major. Batched via blockIdx.z with strides.
// W/bias batch index = z % wMod.
__global__ void k_gemm_nt(const float* __restrict__ A, const float* __restrict__ W,
                          const float* __restrict__ bias, float* __restrict__ C,
                          int M, int Nc, int K,
                          long sAz, long sWz, int wMod, long sCz,
                          const float* __restrict__ alpha_ptr, int mask) {
    int z = blockIdx.z;
    const float* Az = A + (long)z * sAz;
    float*       Cz = C + (long)z * sCz;
    int wz = z % wMod;
    const float* Wz = W + (long)wz * sWz;
    int m0 = blockIdx.y * 64, n0 = blockIdx.x * 64;
    __shared__ float As[64][17];
    __shared__ float Ws[64][17];
    int tx = threadIdx.x, ty = threadIdx.y;
    int tid = ty * 16 + tx;
    int lr = tid >> 2, lc = (tid & 3) << 2;
    float acc[4][4] = {};
    for (int k0 = 0; k0 < K; k0 += 16) {
        float4 a4 = *(const float4*)(Az + (long)(m0 + lr) * K + k0 + lc);
        As[lr][lc + 0] = a4.x; As[lr][lc + 1] = a4.y;
        As[lr][lc + 2] = a4.z; As[lr][lc + 3] = a4.w;
        float4 w4 = make_float4(0.f, 0.f, 0.f, 0.f);
        if (n0 + lr < Nc) w4 = *(const float4*)(Wz + (long)(n0 + lr) * K + k0 + lc);
        Ws[lr][lc + 0] = w4.x; Ws[lr][lc + 1] = w4.y;
        Ws[lr][lc + 2] = w4.z; Ws[lr][lc + 3] = w4.w;
        __syncthreads();
#pragma unroll
        for (int kk = 0; kk < 16; kk++) {
            float av[4], wv[4];
#pragma unroll
            for (int i = 0; i < 4; i++) { av[i] = As[ty * 4 + i][kk]; wv[i] = Ws[tx * 4 + i][kk]; }
#pragma unroll
            for (int i = 0; i < 4; i++)
#pragma unroll
                for (int j = 0; j < 4; j++) acc[i][j] += av[i] * wv[j];
        }
        __syncthreads();
    }
    float alpha = alpha_ptr ? *alpha_ptr : 0.f;
#pragma unroll
    for (int i = 0; i < 4; i++) {
        int row = m0 + ty * 4 + i;
#pragma unroll
        for (int j = 0; j < 4; j++) {
            int col = n0 + tx * 4 + j;
            if (col < Nc && row < M) {
                float c = acc[i][j];
                if (bias) c += bias[wz * Nc + col];
                if (mask) c = (row > col) ? INV_GAMMA * c : 0.f;
                if (alpha_ptr) c = (c >= 0.f) ? c : alpha * c;
                Cz[(long)row * Nc + col] = c;
            }
        }
    }
}

// ---------------- NN GEMM: C = A @ B (A:[M,K], B:[K,Nc], row-major) -------------
__global__ void k_gemm_nn(const float* __restrict__ A, const float* __restrict__ Bm,
                          float* __restrict__ C, int M, int Nc, int K,
                          long sAz, long sBz, long sCz) {
    int z = blockIdx.z;
    const float* Az = A  + (long)z * sAz;
    const float* Bz = Bm + (long)z * sBz;
    float*       Cz = C  + (long)z * sCz;
    int m0 = blockIdx.y * 64, n0 = blockIdx.x * 64;
    __shared__ float As[64][17];
    __shared__ float Bs[16][68];
    int tx = threadIdx.x, ty = threadIdx.y;
    int tid = ty * 16 + tx;
    int lar = tid >> 2, lac = (tid & 3) << 2;
    int lbk = tid >> 4, lbn = (tid & 15) << 2;
    float acc[4][4] = {};
    for (int k0 = 0; k0 < K; k0 += 16) {
        float4 a4 = *(const float4*)(Az + (long)(m0 + lar) * K + k0 + lac);
        As[lar][lac + 0] = a4.x; As[lar][lac + 1] = a4.y;
        As[lar][lac + 2] = a4.z; As[lar][lac + 3] = a4.w;
        float4 b4 = *(const float4*)(Bz + (long)(k0 + lbk) * Nc + n0 + lbn);
        Bs[lbk][lbn + 0] = b4.x; Bs[lbk][lbn + 1] = b4.y;
        Bs[lbk][lbn + 2] = b4.z; Bs[lbk][lbn + 3] = b4.w;
        __syncthreads();
#pragma unroll
        for (int kk = 0; kk < 16; kk++) {
            float av[4], bv[4];
#pragma unroll
            for (int i = 0; i < 4; i++) { av[i] = As[ty * 4 + i][kk]; bv[i] = Bs[kk][tx * 4 + i]; }
#pragma unroll
            for (int i = 0; i < 4; i++)
#pragma unroll
                for (int j = 0; j < 4; j++) acc[i][j] += av[i] * bv[j];
        }
        __syncthreads();
    }
#pragma unroll
    for (int i = 0; i < 4; i++) {
        int row = m0 + ty * 4 + i;
#pragma unroll
        for (int j = 0; j < 4; j++) {
            int col = n0 + tx * 4 + j;
            if (col < Nc && row < M) Cz[(long)row * Nc + col] = acc[i][j];
        }
    }
}

// ---------------- conv over relations + PReLU: u[b,s,n,o] ----------------
__global__ void k_conv(const float* __restrict__ diff, const float* __restrict__ cw,
                       const float* __restrict__ cb, const float* __restrict__ a1,
                       int l, float* __restrict__ u) {
    int i = blockIdx.x * 256 + threadIdx.x;
    if (i >= K_B * K_R * K_N * K_F) return;
    int p = i % (K_N * K_F);
    int s = (i / (K_N * K_F)) % K_R;
    int b = i / (K_N * K_F * K_R);
    float acc = cb[l * K_R + s];
#pragma unroll
    for (int r = 0; r < K_R; r++)
        acc += cw[(l * K_R + s) * K_R + r] * diff[(long)(b * K_R + r) * K_N * K_F + p];
    float al = a1[l];
    u[i] = (acc >= 0.f) ? acc : al * acc;
}

// ---------------- initial skip: skip[b,n,r*F+d] = x[b,r,n,d] ----------------
__global__ void k_skip0(const float* __restrict__ x, float* __restrict__ sk) {
    int i = blockIdx.x * 256 + threadIdx.x;
    if (i >= K_B * K_N * K_R * K_F) return;
    int d = i % K_F;
    int r = (i / K_F) % K_R;
    int n = (i / (K_F * K_R)) % K_N;
    int b = i / (K_F * K_R * K_N);
    sk[i] = x[(((long)b * K_R + r) * K_N + n) * K_F + d];
}

// ---------------- concat [eta | ts] ----------------
__global__ void k_concat(const float* __restrict__ eta, const float* __restrict__ ts,
                         float* __restrict__ cat) {
    int i = blockIdx.x * 256 + threadIdx.x;
    if (i >= K_B * K_N * K_CAT) return;
    int c = i % K_CAT;
    int bn = i / K_CAT;
    cat[i] = (c < K_OUTRET) ? eta[bn * K_OUTRET + c] : ts[bn * K_H1 + (c - K_OUTRET)];
}

// ---------------- host launcher ----------------
extern "C" void kernel_launch(void* const* d_in, const int* in_sizes, int n_in,
                              void* d_out, int out_size) {
    const float* x      = (const float*)d_in[0];
    const float* a      = (const float*)d_in[1];
    const float* T      = (const float*)d_in[2];
    const float* theta  = (const float*)d_in[3];
    const float* fc_w   = (const float*)d_in[4];
    const float* fc_b   = (const float*)d_in[5];
    const float* conv_w = (const float*)d_in[6];
    const float* conv_b = (const float*)d_in[7];
    const float* a0     = (const float*)d_in[8];
    const float* a1     = (const float*)d_in[9];
    const float* qw = (const float*)d_in[10]; const float* qb = (const float*)d_in[11];
    const float* kw = (const float*)d_in[12]; const float* kb = (const float*)d_in[13];
    const float* vw = (const float*)d_in[14]; const float* vb = (const float*)d_in[15];
    const float* rw = (const float*)d_in[16]; const float* rb = (const float*)d_in[17];
    const float* a_ret = (const float*)d_in[18];
    const float* l1w = (const float*)d_in[19]; const float* l1b = (const float*)d_in[20];
    const float* l2w = (const float*)d_in[21]; const float* l2b = (const float*)d_in[22];
    const float* m1w = (const float*)d_in[23]; const float* m1b = (const float*)d_in[24];
    const float* m2w = (const float*)d_in[25]; const float* m2b = (const float*)d_in[26];
    const float* a_mlp = (const float*)d_in[27];
    float* out = (float*)d_out;

    float *S, *feats, *diff, *h, *q, *k, *v, *ms, *ret, *eta, *ts, *cat, *skA, *skB, *m1;
    cudaGetSymbolAddress((void**)&S, g_S);
    cudaGetSymbolAddress((void**)&feats, g_feats);
    cudaGetSymbolAddress((void**)&diff, g_diff);
    cudaGetSymbolAddress((void**)&h, g_h);
    cudaGetSymbolAddress((void**)&q, g_q);
    cudaGetSymbolAddress((void**)&k, g_k);
    cudaGetSymbolAddress((void**)&v, g_v);
    cudaGetSymbolAddress((void**)&ms, g_ms);
    cudaGetSymbolAddress((void**)&ret, g_ret);
    cudaGetSymbolAddress((void**)&eta, g_eta);
    cudaGetSymbolAddress((void**)&ts, g_ts);
    cudaGetSymbolAddress((void**)&cat, g_cat);
    cudaGetSymbolAddress((void**)&skA, g_skipA);
    cudaGetSymbolAddress((void**)&skB, g_skipB);
    cudaGetSymbolAddress((void**)&m1, g_m1);

    dim3 blk(16, 16);
    const int M2 = K_B * K_N; // 2048

    { int tot = K_B * K_N * K_R * K_F;
      k_skip0<<<(tot + 255) / 256, 256>>>(x, skA); }

    const float* hc = x;
    float* sin = skA;
    float* sout = skB;

    for (int l = 0; l < 2; l++) {
        long totS = (long)K_R * K_N * K_N / 4;
        k_S<<<(int)((totS + 255) / 256), 256>>>(T, theta, S, l);

        k_feats<<<dim3(1, K_N / 64, K_B * K_R), blk>>>(S, a, hc, feats);

        // fc + PReLU(a0): per (b,r) GEMM [1024,64]x[64,64]^T
        k_gemm_nt<<<dim3(1, K_N / 64, K_B * K_R), blk>>>(
            feats, fc_w + (long)l * K_R * K_F * K_F, fc_b + l * K_R * K_F, diff,
            K_N, K_F, K_F, (long)K_N * K_F, (long)K_F * K_F, K_R, (long)K_N * K_F,
            a0 + l, 0);

        { int tot = K_B * K_R * K_N * K_F;
          k_conv<<<(tot + 255) / 256, 256>>>(diff, conv_w, conv_b, a1, l, h); }
        hc = h;

        // q,k,v: xr is the raw reshape of h -> [2048, 320]
        k_gemm_nt<<<dim3(K_INTER / 64, M2 / 64, 1), blk>>>(
            h, qw + (long)l * K_INTER * K_INRET, qb + l * K_INTER, q,
            M2, K_INTER, K_INRET, 0, 0, 1, 0, nullptr, 0);
        k_gemm_nt<<<dim3(K_INTER / 64, M2 / 64, 1), blk>>>(
            h, kw + (long)l * K_INTER * K_INRET, kb + l * K_INTER, k,
            M2, K_INTER, K_INRET, 0, 0, 1, 0, nullptr, 0);
        k_gemm_nt<<<dim3(K_INTER / 64, M2 / 64, 1), blk>>>(
            h, vw + (long)l * K_INTER * K_INRET, vb + l * K_INTER, v,
            M2, K_INTER, K_INRET, 0, 0, 1, 0, nullptr, 0);

        // masked scores: ms[b,t,s] = (t>s) ? 0.4 * q[t]·k[s] : 0
        k_gemm_nt<<<dim3(K_N / 64, K_N / 64, K_B), blk>>>(
            q, k, nullptr, ms,
            K_N, K_N, K_INTER, (long)K_N * K_INTER, (long)K_N * K_INTER, K_B,
            (long)K_N * K_N, nullptr, 1);

        // ret = ms @ v
        k_gemm_nn<<<dim3(K_OUTRET / 64, K_N / 64, K_B), blk>>>(
            ms, v, ret, K_N, K_OUTRET, K_N,
            (long)K_N * K_N, (long)K_N * K_INTER, (long)K_N * K_OUTRET);

        // eta = PReLU(ret @ rw^T + rb, a_ret)
        k_gemm_nt<<<dim3(K_OUTRET / 64, M2 / 64, 1), blk>>>(
            ret, rw + (long)l * K_OUTRET * K_INTER, rb + l * K_OUTRET, eta,
            M2, K_OUTRET, K_INTER, 0, 0, 1, 0, a_ret + l, 0);

        // ts = skip @ l1^T + l1_b
        k_gemm_nt<<<dim3(K_H1 / 64, M2 / 64, 1), blk>>>(
            sin, l1w + (long)l * K_H1 * K_HRET, l1b + l * K_H1, ts,
            M2, K_H1, K_HRET, 0, 0, 1, 0, nullptr, 0);

        { int tot = K_B * K_N * K_CAT;
          k_concat<<<(tot + 255) / 256, 256>>>(eta, ts, cat); }

        // skip' = cat @ l2^T + l2_b
        k_gemm_nt<<<dim3(K_HRET / 64, M2 / 64, 1), blk>>>(
            cat, l2w + (long)l * K_HRET * K_CAT, l2b + l * K_HRET, sout,
            M2, K_HRET, K_CAT, 0, 0, 1, 0, nullptr, 0);

        float* t0 = sin; sin = sout; sout = t0;
    }

    // final MLP
    k_gemm_nt<<<dim3(K_H1 / 64, M2 / 64, 1), blk>>>(
        sin, m1w, m1b, m1, M2, K_H1, K_HRET, 0, 0, 1, 0, a_mlp, 0);
    k_gemm_nt<<<dim3(1, M2 / 64, 1), blk>>>(
        m1, m2w, m2b, out, M2, K_NCLS, K_H1, 0, 0, 1, 0, nullptr, 0);
}

// round 2
// speedup vs baseline: 1.3004x; 1.3004x over previous
#include <cuda_runtime.h>

#define K_B 2
#define K_R 5
#define K_N 1024
#define K_E 3
#define K_F 64
#define K_INRET 320
#define K_INTER 256
#define K_OUTRET 256
#define K_H1 128
#define K_HRET 320
#define K_CAT 384
#define INV_GAMMA 0.4f

typedef unsigned long long ull;

__device__ __forceinline__ ull pack2(float lo, float hi) {
    ull r; asm("mov.b64 %0, {%1, %2};" : "=l"(r) : "f"(lo), "f"(hi)); return r;
}
__device__ __forceinline__ void fma2(ull& c, ull a, ull b) {
    asm("fma.rn.f32x2 %0, %1, %2, %3;" : "=l"(c) : "l"(a), "l"(b), "l"(c));
}
__device__ __forceinline__ float2 unpack2(ull v) {
    float lo, hi; asm("mov.b64 {%0, %1}, %2;" : "=f"(lo), "=f"(hi) : "l"(v));
    return make_float2(lo, hi);
}

// ---------------- device scratch ----------------
__device__ float g_feats[K_B * K_R * K_N * K_F];
__device__ float g_diff [K_B * K_R * K_N * K_F];
__device__ float g_h    [K_B * K_R * K_N * K_F];
__device__ float g_q [K_B * K_N * K_INTER];
__device__ float g_k [K_B * K_N * K_INTER];
__device__ float g_v [K_B * K_N * K_INTER];
__device__ float g_ms[K_B * K_N * K_N];
__device__ float g_ret[K_B * K_N * K_OUTRET];
__device__ float g_cat[K_B * K_N * K_CAT];
__device__ float g_skipA[K_B * K_N * K_HRET];
__device__ float g_skipB[K_B * K_N * K_HRET];
__device__ float g_m1[K_B * K_N * K_H1];

// =====================================================================
// Generic GEMM: C = act(A @ op(B) + bias), f32x2 packed accumulators.
//   A: [M,K] row-major (ldA = K). TRANSB: B [Nc,K]; else B [K,Nc].
//   mode 1: D_gamma score mask (row>col ? c/gamma : 0), zero-block skip.
//   mode 2: K-limit to min(K, m0+BM) (causal right operand is zero beyond).
// =====================================================================
template<int BM, int BN, int TM, int TN, bool TRANSB>
__global__ void __launch_bounds__(256, 2) k_gemm(
    const float* __restrict__ A, const float* __restrict__ B,
    const float* __restrict__ bias, float* __restrict__ C,
    int M, int Nc, int K,
    long sAz, long sBz, int bMod, long sCz,
    int ldC, const float* __restrict__ alpha_ptr, int mode)
{
    constexpr int BK = 16, PAD = 4;
    constexpr int AIT = (BM * BK / 4) / 256;
    constexpr int BIT = (BN * BK / 4) / 256;
    __shared__ float As[BK][BM + PAD];
    __shared__ float Bs[BK][BN + PAD];

    int z = blockIdx.z;
    const float* Az = A + (long)z * sAz;
    int wz = z % bMod;
    const float* Bz = B + (long)wz * sBz;
    float* Cz = C + (long)z * sCz;
    int m0 = blockIdx.y * BM, n0 = blockIdx.x * BN;
    int tid = threadIdx.x;
    int tx = tid & 15, ty = tid >> 4;

    if (mode == 1 && (m0 + BM - 1 <= n0)) {
        // fully above diagonal: all zeros
#pragma unroll
        for (int i = 0; i < TM; i++) {
            long base = (long)(m0 + ty * TM + i) * ldC + n0 + tx * TN;
#pragma unroll
            for (int j = 0; j < TN; j += 4)
                *(float4*)&Cz[base + j] = make_float4(0.f, 0.f, 0.f, 0.f);
        }
        return;
    }
    int Kend = K;
    if (mode == 2) Kend = min(K, m0 + BM);

    ull acc[TM / 2][TN];
#pragma unroll
    for (int i = 0; i < TM / 2; i++)
#pragma unroll
        for (int j = 0; j < TN; j++) acc[i][j] = 0ULL;

    float4 areg[AIT], breg[BIT];
    // initial global loads (k0 = 0)
#pragma unroll
    for (int t = 0; t < AIT; t++) {
        int idx = tid + t * 256; int row = idx >> 2, q = idx & 3;
        areg[t] = *(const float4*)&Az[(long)(m0 + row) * K + q * 4];
    }
    if (TRANSB) {
#pragma unroll
        for (int t = 0; t < BIT; t++) {
            int idx = tid + t * 256; int row = idx >> 2, q = idx & 3;
            breg[t] = *(const float4*)&Bz[(long)(n0 + row) * K + q * 4];
        }
    } else {
#pragma unroll
        for (int t = 0; t < BIT; t++) {
            int idx = tid + t * 256; int c = idx & (BN / 4 - 1), kk = idx / (BN / 4);
            breg[t] = *(const float4*)&Bz[(long)kk * Nc + n0 + c * 4];
        }
    }

    for (int k0 = 0; k0 < Kend; k0 += BK) {
        // stage regs -> smem (k-major)
#pragma unroll
        for (int t = 0; t < AIT; t++) {
            int idx = tid + t * 256; int row = idx >> 2, q = idx & 3;
            As[q * 4 + 0][row] = areg[t].x; As[q * 4 + 1][row] = areg[t].y;
            As[q * 4 + 2][row] = areg[t].z; As[q * 4 + 3][row] = areg[t].w;
        }
        if (TRANSB) {
#pragma unroll
            for (int t = 0; t < BIT; t++) {
                int idx = tid + t * 256; int row = idx >> 2, q = idx & 3;
                Bs[q * 4 + 0][row] = breg[t].x; Bs[q * 4 + 1][row] = breg[t].y;
                Bs[q * 4 + 2][row] = breg[t].z; Bs[q * 4 + 3][row] = breg[t].w;
            }
        } else {
#pragma unroll
            for (int t = 0; t < BIT; t++) {
                int idx = tid + t * 256; int c = idx & (BN / 4 - 1), kk = idx / (BN / 4);
                *(float4*)&Bs[kk][c * 4] = breg[t];
            }
        }
        __syncthreads();

        int kn = k0 + BK;
        if (kn < Kend) {  // prefetch next chunk
#pragma unroll
            for (int t = 0; t < AIT; t++) {
                int idx = tid + t * 256; int row = idx >> 2, q = idx & 3;
                areg[t] = *(const float4*)&Az[(long)(m0 + row) * K + kn + q * 4];
            }
            if (TRANSB) {
#pragma unroll
                for (int t = 0; t < BIT; t++) {
                    int idx = tid + t * 256; int row = idx >> 2, q = idx & 3;
                    breg[t] = *(const float4*)&Bz[(long)(n0 + row) * K + kn + q * 4];
                }
            } else {
#pragma unroll
                for (int t = 0; t < BIT; t++) {
                    int idx = tid + t * 256; int c = idx & (BN / 4 - 1), kk = idx / (BN / 4);
                    breg[t] = *(const float4*)&Bz[(long)(kn + kk) * Nc + n0 + c * 4];
                }
            }
        }

#pragma unroll
        for (int kk = 0; kk < BK; kk++) {
            ull aP[TM / 2];
#pragma unroll
            for (int i = 0; i < TM / 2; i++)
                aP[i] = *(const ull*)&As[kk][ty * TM + 2 * i];
            float bv[TN];
#pragma unroll
            for (int j = 0; j < TN; j += 4)
                *(float4*)&bv[j] = *(const float4*)&Bs[kk][tx * TN + j];
            ull bR[TN];
#pragma unroll
            for (int j = 0; j < TN; j++) bR[j] = pack2(bv[j], bv[j]);
#pragma unroll
            for (int i = 0; i < TM / 2; i++)
#pragma unroll
                for (int j = 0; j < TN; j++) fma2(acc[i][j], aP[i], bR[j]);
        }
        __syncthreads();
    }

    float alpha = alpha_ptr ? *alpha_ptr : 0.f;
    bool prelu = (alpha_ptr != nullptr);
#pragma unroll
    for (int i = 0; i < TM / 2; i++) {
        int row0 = m0 + ty * TM + 2 * i;
        float r0[TN], r1[TN];
#pragma unroll
        for (int j = 0; j < TN; j++) {
            float2 p = unpack2(acc[i][j]); r0[j] = p.x; r1[j] = p.y;
        }
#pragma unroll
        for (int j = 0; j < TN; j++) {
            int col = n0 + tx * TN + j;
            if (bias) { float bb = bias[wz * Nc + col]; r0[j] += bb; r1[j] += bb; }
            if (mode == 1) {
                r0[j] = (row0 > col)     ? INV_GAMMA * r0[j] : 0.f;
                r1[j] = (row0 + 1 > col) ? INV_GAMMA * r1[j] : 0.f;
            }
            if (prelu) {
                r0[j] = (r0[j] >= 0.f) ? r0[j] : alpha * r0[j];
                r1[j] = (r1[j] >= 0.f) ? r1[j] : alpha * r1[j];
            }
        }
#pragma unroll
        for (int j = 0; j < TN; j += 4) {
            *(float4*)&Cz[(long)row0 * ldC + n0 + tx * TN + j]       = *(float4*)&r0[j];
            *(float4*)&Cz[(long)(row0 + 1) * ldC + n0 + tx * TN + j] = *(float4*)&r1[j];
        }
    }
}

// =====================================================================
// feats[b,r] = ((sum_e theta_e * T_e) .* a[b,r]) @ h[b,r]   (fused S)
// BM=64, BN=64(=F), TM=TN=4, NN orientation.
// =====================================================================
__global__ void __launch_bounds__(256, 2) k_feats(
    const float* __restrict__ Tm, const float* __restrict__ theta,
    const float* __restrict__ Ab, const float* __restrict__ H,
    float* __restrict__ out, int l)
{
    constexpr int BM = 64, BK = 16, PAD = 4;
    __shared__ float As[BK][BM + PAD];
    __shared__ float Bs[BK][BM + PAD];
    int z = blockIdx.z; int r = z % K_R;
    const float* T0 = Tm + (long)((l * K_R + r) * K_E) * K_N * K_N;
    const float* T1 = T0 + (long)K_N * K_N;
    const float* T2 = T1 + (long)K_N * K_N;
    const float* Az = Ab + (long)z * K_N * K_N;
    const float* Hz = H  + (long)z * K_N * K_F;
    float* Cz = out + (long)z * K_N * K_F;
    float t0 = theta[(l * K_R + r) * K_E + 0];
    float t1 = theta[(l * K_R + r) * K_E + 1];
    float t2 = theta[(l * K_R + r) * K_E + 2];
    int m0 = blockIdx.y * BM;
    int tid = threadIdx.x, tx = tid & 15, ty = tid >> 4;
    int arow = tid >> 2, aq = tid & 3;
    int bc = tid & 15, bk = tid >> 4;

    ull acc[2][4];
#pragma unroll
    for (int i = 0; i < 2; i++)
#pragma unroll
        for (int j = 0; j < 4; j++) acc[i][j] = 0ULL;

    float4 areg, breg;
    {
        long off = (long)(m0 + arow) * K_N + aq * 4;
        float4 v0 = *(const float4*)(T0 + off), v1 = *(const float4*)(T1 + off);
        float4 v2 = *(const float4*)(T2 + off), a4 = *(const float4*)(Az + off);
        areg.x = (t0 * v0.x + t1 * v1.x + t2 * v2.x) * a4.x;
        areg.y = (t0 * v0.y + t1 * v1.y + t2 * v2.y) * a4.y;
        areg.z = (t0 * v0.z + t1 * v1.z + t2 * v2.z) * a4.z;
        areg.w = (t0 * v0.w + t1 * v1.w + t2 * v2.w) * a4.w;
        breg = *(const float4*)&Hz[(long)bk * K_F + bc * 4];
    }
    for (int k0 = 0; k0 < K_N; k0 += BK) {
        As[aq * 4 + 0][arow] = areg.x; As[aq * 4 + 1][arow] = areg.y;
        As[aq * 4 + 2][arow] = areg.z; As[aq * 4 + 3][arow] = areg.w;
        *(float4*)&Bs[bk][bc * 4] = breg;
        __syncthreads();
        int kn = k0 + BK;
        if (kn < K_N) {
            long off = (long)(m0 + arow) * K_N + kn + aq * 4;
            float4 v0 = *(const float4*)(T0 + off), v1 = *(const float4*)(T1 + off);
            float4 v2 = *(const float4*)(T2 + off), a4 = *(const float4*)(Az + off);
            areg.x = (t0 * v0.x + t1 * v1.x + t2 * v2.x) * a4.x;
            areg.y = (t0 * v0.y + t1 * v1.y + t2 * v2.y) * a4.y;
            areg.z = (t0 * v0.z + t1 * v1.z + t2 * v2.z) * a4.z;
            areg.w = (t0 * v0.w + t1 * v1.w + t2 * v2.w) * a4.w;
            breg = *(const float4*)&Hz[(long)(kn + bk) * K_F + bc * 4];
        }
#pragma unroll
        for (int kk = 0; kk < BK; kk++) {
            ull aP[2];
            aP[0] = *(const ull*)&As[kk][ty * 4];
            aP[1] = *(const ull*)&As[kk][ty * 4 + 2];
            float bv[4];
            *(float4*)bv = *(const float4*)&Bs[kk][tx * 4];
            ull bR[4];
#pragma unroll
            for (int j = 0; j < 4; j++) bR[j] = pack2(bv[j], bv[j]);
#pragma unroll
            for (int i = 0; i < 2; i++)
#pragma unroll
                for (int j = 0; j < 4; j++) fma2(acc[i][j], aP[i], bR[j]);
        }
        __syncthreads();
    }
#pragma unroll
    for (int i = 0; i < 2; i++) {
        int row0 = m0 + ty * 4 + 2 * i;
        float r0[4], r1[4];
#pragma unroll
        for (int j = 0; j < 4; j++) {
            float2 p = unpack2(acc[i][j]); r0[j] = p.x; r1[j] = p.y;
        }
        *(float4*)&Cz[(long)row0 * K_F + tx * 4]       = *(float4*)r0;
        *(float4*)&Cz[(long)(row0 + 1) * K_F + tx * 4] = *(float4*)r1;
    }
}

// ---------------- conv over relations + PReLU (vectorized) ----------------
__global__ void k_conv(const float* __restrict__ diff, const float* __restrict__ cw,
                       const float* __restrict__ cb, const float* __restrict__ a1,
                       int l, float* __restrict__ u) {
    const int PQ = K_N * K_F / 4;
    int i = blockIdx.x * 256 + threadIdx.x;
    if (i >= K_B * K_R * PQ) return;
    int pq = i % PQ; int s = (i / PQ) % K_R; int b = i / (PQ * K_R);
    float bb = cb[l * K_R + s];
    float4 acc = make_float4(bb, bb, bb, bb);
    const float4* d4 = (const float4*)diff;
#pragma unroll
    for (int r2 = 0; r2 < K_R; r2++) {
        float w = cw[(l * K_R + s) * K_R + r2];
        float4 v = d4[(long)(b * K_R + r2) * PQ + pq];
        acc.x += w * v.x; acc.y += w * v.y; acc.z += w * v.z; acc.w += w * v.w;
    }
    float al = a1[l];
    acc.x = (acc.x >= 0.f) ? acc.x : al * acc.x;
    acc.y = (acc.y >= 0.f) ? acc.y : al * acc.y;
    acc.z = (acc.z >= 0.f) ? acc.z : al * acc.z;
    acc.w = (acc.w >= 0.f) ? acc.w : al * acc.w;
    ((float4*)u)[i] = acc;
}

// ---------------- initial skip transpose ----------------
__global__ void k_skip0(const float* __restrict__ x, float* __restrict__ sk) {
    int i = blockIdx.x * 256 + threadIdx.x;
    if (i >= K_B * K_N * K_R * K_F) return;
    int d = i % K_F;
    int r = (i / K_F) % K_R;
    int n = (i / (K_F * K_R)) % K_N;
    int b = i / (K_F * K_R * K_N);
    sk[i] = x[(((long)b * K_R + r) * K_N + n) * K_F + d];
}

// ---------------- final tiny GEMM: out[2048,2] ----------------
__global__ void k_mlp2(const float* __restrict__ m1, const float* __restrict__ w,
                       const float* __restrict__ b, float* __restrict__ out) {
    __shared__ float ws[2 * K_H1];
    int tid = threadIdx.x;
    if (tid < 2 * K_H1) ws[tid] = w[tid];
    __syncthreads();
    int row = blockIdx.x * 256 + tid;
    const float4* mr = (const float4*)(m1 + (long)row * K_H1);
    float s0 = 0.f, s1 = 0.f;
#pragma unroll
    for (int i = 0; i < K_H1 / 4; i++) {
        float4 v = mr[i];
        s0 += v.x * ws[i * 4] + v.y * ws[i * 4 + 1] + v.z * ws[i * 4 + 2] + v.w * ws[i * 4 + 3];
        s1 += v.x * ws[K_H1 + i * 4] + v.y * ws[K_H1 + i * 4 + 1]
            + v.z * ws[K_H1 + i * 4 + 2] + v.w * ws[K_H1 + i * 4 + 3];
    }
    out[(long)row * 2]     = s0 + b[0];
    out[(long)row * 2 + 1] = s1 + b[1];
}

// ---------------- host launcher ----------------
extern "C" void kernel_launch(void* const* d_in, const int* in_sizes, int n_in,
                              void* d_out, int out_size) {
    const float* x      = (const float*)d_in[0];
    const float* a      = (const float*)d_in[1];
    const float* T      = (const float*)d_in[2];
    const float* theta  = (const float*)d_in[3];
    const float* fc_w   = (const float*)d_in[4];
    const float* fc_b   = (const float*)d_in[5];
    const float* conv_w = (const float*)d_in[6];
    const float* conv_b = (const float*)d_in[7];
    const float* a0     = (const float*)d_in[8];
    const float* a1     = (const float*)d_in[9];
    const float* qw = (const float*)d_in[10]; const float* qb = (const float*)d_in[11];
    const float* kw = (const float*)d_in[12]; const float* kb = (const float*)d_in[13];
    const float* vw = (const float*)d_in[14]; const float* vb = (const float*)d_in[15];
    const float* rw = (const float*)d_in[16]; const float* rb = (const float*)d_in[17];
    const float* a_ret = (const float*)d_in[18];
    const float* l1w = (const float*)d_in[19]; const float* l1b = (const float*)d_in[20];
    const float* l2w = (const float*)d_in[21]; const float* l2b = (const float*)d_in[22];
    const float* m1w = (const float*)d_in[23]; const float* m1b = (const float*)d_in[24];
    const float* m2w = (const float*)d_in[25]; const float* m2b = (const float*)d_in[26];
    const float* a_mlp = (const float*)d_in[27];
    float* out = (float*)d_out;

    float *feats, *diff, *h, *q, *k, *v, *ms, *ret, *cat, *skA, *skB, *m1;
    cudaGetSymbolAddress((void**)&feats, g_feats);
    cudaGetSymbolAddress((void**)&diff, g_diff);
    cudaGetSymbolAddress((void**)&h, g_h);
    cudaGetSymbolAddress((void**)&q, g_q);
    cudaGetSymbolAddress((void**)&k, g_k);
    cudaGetSymbolAddress((void**)&v, g_v);
    cudaGetSymbolAddress((void**)&ms, g_ms);
    cudaGetSymbolAddress((void**)&ret, g_ret);
    cudaGetSymbolAddress((void**)&cat, g_cat);
    cudaGetSymbolAddress((void**)&skA, g_skipA);
    cudaGetSymbolAddress((void**)&skB, g_skipB);
    cudaGetSymbolAddress((void**)&m1, g_m1);

    const int M2 = K_B * K_N;  // 2048

    { int tot = K_B * K_N * K_R * K_F;
      k_skip0<<<(tot + 255) / 256, 256>>>(x, skA); }

    const float* hc = x;
    float* sin_ = skA;
    float* sout = skB;

    for (int l = 0; l < 2; l++) {
        // diffusion GEMM with fused S (10 z-batches)
        k_feats<<<dim3(1, K_N / 64, K_B * K_R), 256>>>(T, theta, a, hc, feats, l);

        // fc + PReLU(a0)
        k_gemm<64, 64, 4, 4, true><<<dim3(1, K_N / 64, K_B * K_R), 256>>>(
            feats, fc_w + (long)l * K_R * K_F * K_F, fc_b + l * K_R * K_F, diff,
            K_N, K_F, K_F, (long)K_N * K_F, (long)K_F * K_F, K_R, (long)K_N * K_F,
            K_F, a0 + l, 0);

        { int tot = K_B * K_R * K_N * K_F / 4;
          k_conv<<<(tot + 255) / 256, 256>>>(diff, conv_w, conv_b, a1, l, h); }
        hc = h;

        // q,k,v projections (xr = raw reshape of h -> [2048,320])
        k_gemm<128, 64, 8, 4, true><<<dim3(K_INTER / 64, M2 / 128, 1), 256>>>(
            h, qw + (long)l * K_INTER * K_INRET, qb + l * K_INTER, q,
            M2, K_INTER, K_INRET, 0, 0, 1, 0, K_INTER, nullptr, 0);
        k_gemm<128, 64, 8, 4, true><<<dim3(K_INTER / 64, M2 / 128, 1), 256>>>(
            h, kw + (long)l * K_INTER * K_INRET, kb + l * K_INTER, k,
            M2, K_INTER, K_INRET, 0, 0, 1, 0, K_INTER, nullptr, 0);
        k_gemm<128, 64, 8, 4, true><<<dim3(K_INTER / 64, M2 / 128, 1), 256>>>(
            h, vw + (long)l * K_INTER * K_INRET, vb + l * K_INTER, v,
            M2, K_INTER, K_INRET, 0, 0, 1, 0, K_INTER, nullptr, 0);

        // masked scores: D_gamma * (q @ k^T); zero-blocks skipped
        k_gemm<128, 128, 8, 8, true><<<dim3(K_N / 128, K_N / 128, K_B), 256>>>(
            q, k, nullptr, ms,
            K_N, K_N, K_INTER, (long)K_N * K_INTER, (long)K_N * K_INTER, K_B,
            (long)K_N * K_N, K_N, nullptr, 1);

        // ret = ms @ v, K limited to the causal range
        k_gemm<64, 64, 4, 4, false><<<dim3(K_OUTRET / 64, K_N / 64, K_B), 256>>>(
            ms, v, nullptr, ret,
            K_N, K_OUTRET, K_N, (long)K_N * K_N, (long)K_N * K_INTER, K_B,
            (long)K_N * K_OUTRET, K_OUTRET, nullptr, 2);

        // eta -> cat[:, 0:256] (PReLU a_ret)
        k_gemm<64, 64, 4, 4, true><<<dim3(K_OUTRET / 64, M2 / 64, 1), 256>>>(
            ret, rw + (long)l * K_OUTRET * K_INTER, rb + l * K_OUTRET, cat,
            M2, K_OUTRET, K_INTER, 0, 0, 1, 0, K_CAT, a_ret + l, 0);

        // ts -> cat[:, 256:384]
        k_gemm<64, 64, 4, 4, true><<<dim3(K_H1 / 64, M2 / 64, 1), 256>>>(
            sin_, l1w + (long)l * K_H1 * K_HRET, l1b + l * K_H1, cat + K_OUTRET,
            M2, K_H1, K_HRET, 0, 0, 1, 0, K_CAT, nullptr, 0);

        // skip' = cat @ l2^T + l2_b
        k_gemm<64, 64, 4, 4, true><<<dim3(K_HRET / 64, M2 / 64, 1), 256>>>(
            cat, l2w + (long)l * K_HRET * K_CAT, l2b + l * K_HRET, sout,
            M2, K_HRET, K_CAT, 0, 0, 1, 0, K_HRET, nullptr, 0);

        float* t0 = sin_; sin_ = sout; sout = t0;
    }

    // final MLP
    k_gemm<64, 64, 4, 4, true><<<dim3(K_H1 / 64, M2 / 64, 1), 256>>>(
        sin_, m1w, m1b, m1, M2, K_H1, K_HRET, 0, 0, 1, 0, K_H1, a_mlp, 0);
    k_mlp2<<<M2 / 256, 256>>>(m1, m2w, m2b, out);
}

// round 3
// speedup vs baseline: 1.6820x; 1.2935x over previous
#include <cuda_runtime.h>

#define K_B 2
#define K_R 5
#define K_N 1024
#define K_E 3
#define K_F 64
#define K_INRET 320
#define K_INTER 256
#define K_OUTRET 256
#define K_H1 128
#define K_HRET 320
#define K_CAT 384
#define INV_GAMMA 0.4f
#define SMS 68   // padded smem row stride (floats)

typedef unsigned long long ull;

__device__ __forceinline__ ull pack2(float lo, float hi) {
    ull r; asm("mov.b64 %0, {%1, %2};" : "=l"(r) : "f"(lo), "f"(hi)); return r;
}
__device__ __forceinline__ void fma2(ull& c, ull a, ull b) {
    asm("fma.rn.f32x2 %0, %1, %2, %3;" : "=l"(c) : "l"(a), "l"(b), "l"(c));
}
__device__ __forceinline__ float2 unpack2(ull v) {
    float lo, hi; asm("mov.b64 {%0, %1}, %2;" : "=f"(lo), "=f"(hi) : "l"(v));
    return make_float2(lo, hi);
}

// ---------------- device scratch ----------------
__device__ float g_featsP[2 * K_B * K_R * K_N * K_F];  // split-K partials
__device__ float g_diff [K_B * K_R * K_N * K_F];
__device__ float g_h    [K_B * K_R * K_N * K_F];
__device__ float g_q [K_B * K_N * K_INTER];
__device__ float g_k [K_B * K_N * K_INTER];
__device__ float g_v [K_B * K_N * K_INTER];
__device__ float g_ms[K_B * K_N * K_N];
__device__ float g_ret[K_B * K_N * K_OUTRET];
__device__ float g_cat[K_B * K_N * K_CAT];
__device__ float g_skipA[K_B * K_N * K_HRET];
__device__ float g_skipB[K_B * K_N * K_HRET];
__device__ float g_m1[K_B * K_N * K_H1];

// ---------------- shared micro-kernel pieces ----------------
__device__ __forceinline__ void stage_q(float* S, int row, int q, float4 v) {
    S[(q * 4 + 0) * SMS + row] = v.x;
    S[(q * 4 + 1) * SMS + row] = v.y;
    S[(q * 4 + 2) * SMS + row] = v.z;
    S[(q * 4 + 3) * SMS + row] = v.w;
}

__device__ __forceinline__ void mma16(const float* As, const float* Bs,
                                      int tx, int ty, ull acc[2][4]) {
#pragma unroll
    for (int kk = 0; kk < 16; kk++) {
        ull a0 = *(const ull*)&As[kk * SMS + ty * 4];
        ull a1 = *(const ull*)&As[kk * SMS + ty * 4 + 2];
        float4 b4 = *(const float4*)&Bs[kk * SMS + tx * 4];
        ull b0 = pack2(b4.x, b4.x), b1 = pack2(b4.y, b4.y);
        ull b2 = pack2(b4.z, b4.z), b3 = pack2(b4.w, b4.w);
        fma2(acc[0][0], a0, b0); fma2(acc[0][1], a0, b1);
        fma2(acc[0][2], a0, b2); fma2(acc[0][3], a0, b3);
        fma2(acc[1][0], a1, b0); fma2(acc[1][1], a1, b1);
        fma2(acc[1][2], a1, b2); fma2(acc[1][3], a1, b3);
    }
}

// NT main loop: A rows [0..64) of Az (ldA), B rows [0..64) of Bz (ldB), K%16==0
template<bool ADD2>
__device__ __forceinline__ void loop_nt(const float* __restrict__ Az, int ldA,
                                        const float* __restrict__ A2z,
                                        const float* __restrict__ Bz, int ldB,
                                        int K, float* As, float* Bs, ull acc[2][4]) {
    int tid = threadIdx.x;
    int r_ = tid >> 2, q_ = tid & 3;
    int tx = tid & 15, ty = tid >> 4;
    float4 ar = *(const float4*)&Az[(long)r_ * ldA + q_ * 4];
    float4 br = *(const float4*)&Bz[(long)r_ * ldB + q_ * 4];
    float4 a2 = make_float4(0.f, 0.f, 0.f, 0.f);
    if (ADD2) a2 = *(const float4*)&A2z[(long)r_ * ldA + q_ * 4];
    for (int k0 = 0; k0 < K; k0 += 16) {
        if (ADD2) { ar.x += a2.x; ar.y += a2.y; ar.z += a2.z; ar.w += a2.w; }
        stage_q(As, r_, q_, ar);
        stage_q(Bs, r_, q_, br);
        __syncthreads();
        int kn = k0 + 16;
        if (kn < K) {
            ar = *(const float4*)&Az[(long)r_ * ldA + kn + q_ * 4];
            br = *(const float4*)&Bz[(long)r_ * ldB + kn + q_ * 4];
            if (ADD2) a2 = *(const float4*)&A2z[(long)r_ * ldA + kn + q_ * 4];
        }
        mma16(As, Bs, tx, ty, acc);
        __syncthreads();
    }
}

// NN main loop: B is [K, ldB] row-major, cols already offset in Bz.
__device__ __forceinline__ void loop_nn(const float* __restrict__ Az, int ldA,
                                        const float* __restrict__ Bz, int ldB,
                                        int K, float* As, float* Bs, ull acc[2][4]) {
    int tid = threadIdx.x;
    int r_ = tid >> 2, q_ = tid & 3;
    int bk = tid >> 4, bc = tid & 15;
    int tx = tid & 15, ty = tid >> 4;
    float4 ar = *(const float4*)&Az[(long)r_ * ldA + q_ * 4];
    float4 br = *(const float4*)&Bz[(long)bk * ldB + bc * 4];
    for (int k0 = 0; k0 < K; k0 += 16) {
        stage_q(As, r_, q_, ar);
        *(float4*)&Bs[bk * SMS + bc * 4] = br;
        __syncthreads();
        int kn = k0 + 16;
        if (kn < K) {
            ar = *(const float4*)&Az[(long)r_ * ldA + kn + q_ * 4];
            br = *(const float4*)&Bz[(long)(kn + bk) * ldB + bc * 4];
        }
        mma16(As, Bs, tx, ty, acc);
        __syncthreads();
    }
}

// Epilogue: bias + optional PReLU, f4 stores. colb = global col of tx*4.
__device__ __forceinline__ void epi_store(float* Cz, int ldC, int row0, int colb,
                                          ull acc[2][4], const float* bias,
                                          float alpha, bool prelu) {
#pragma unroll
    for (int i = 0; i < 2; i++) {
        float r0[4], r1[4];
#pragma unroll
        for (int j = 0; j < 4; j++) {
            float2 p = unpack2(acc[i][j]); r0[j] = p.x; r1[j] = p.y;
            if (bias) { float bb = bias[colb + j]; r0[j] += bb; r1[j] += bb; }
            if (prelu) {
                r0[j] = (r0[j] >= 0.f) ? r0[j] : alpha * r0[j];
                r1[j] = (r1[j] >= 0.f) ? r1[j] : alpha * r1[j];
            }
        }
        int rr = row0 + 2 * i;
        *(float4*)&Cz[(long)rr * ldC + colb]       = *(float4*)r0;
        *(float4*)&Cz[(long)(rr + 1) * ldC + colb] = *(float4*)r1;
    }
}

// =============== generic 64x64 GEMM kernel =====================
template<bool ADD2, bool NN>
__global__ void __launch_bounds__(256, 3) k_gemm64(
    const float* __restrict__ A, const float* __restrict__ A2,
    const float* __restrict__ B, const float* __restrict__ bias,
    float* __restrict__ C, int Nc, int K,
    long sAz, int ldA, long sBz, int ldB, int bMod, long sCz, int ldC,
    const float* __restrict__ alpha_ptr, int causal)
{
    __shared__ float As[16 * SMS];
    __shared__ float Bs[16 * SMS];
    int z = blockIdx.z;
    int m0 = blockIdx.y * 64, n0 = blockIdx.x * 64;
    int wz = z % bMod;
    const float* Az = A + (long)z * sAz + (long)m0 * ldA;
    const float* Bz;
    if (NN) Bz = B + (long)z * sBz + n0;
    else    Bz = B + (long)wz * sBz + (long)n0 * ldB;
    float* Cz = C + (long)z * sCz;
    int Keff = causal ? (m0 + 64) : K;

    ull acc[2][4];
#pragma unroll
    for (int i = 0; i < 2; i++)
#pragma unroll
        for (int j = 0; j < 4; j++) acc[i][j] = 0ULL;

    if (NN) loop_nn(Az, ldA, Bz, ldB, Keff, As, Bs, acc);
    else    loop_nt<ADD2>(Az, ldA, ADD2 ? (A2 + (long)z * sAz + (long)m0 * ldA) : nullptr,
                          Bz, ldB, Keff, As, Bs, acc);

    int tx = threadIdx.x & 15, ty = threadIdx.x >> 4;
    float alpha = alpha_ptr ? *alpha_ptr : 0.f;
    epi_store(Cz, ldC, m0 + ty * 4, n0 + tx * 4, acc,
              bias ? (bias + wz * Nc) : nullptr, alpha, alpha_ptr != nullptr);
}

// =============== feats: fused S, split-K x2 =====================
// z: br = z>>1 (b*5+r), chunk = z&1. Output partial plane (chunk*10+br).
__global__ void __launch_bounds__(256, 3) k_feats(
    const float* __restrict__ Tm, const float* __restrict__ theta,
    const float* __restrict__ Ab, const float* __restrict__ H,
    float* __restrict__ P, int l)
{
    __shared__ float As[16 * SMS];
    __shared__ float Bs[16 * SMS];
    int z = blockIdx.z;
    int br = z >> 1, chunk = z & 1;
    int r = br % K_R;
    const float* T0 = Tm + (long)((l * K_R + r) * K_E) * K_N * K_N;
    const float* T1 = T0 + (long)K_N * K_N;
    const float* T2 = T1 + (long)K_N * K_N;
    const float* Az = Ab + (long)br * K_N * K_N;
    const float* Hz = H  + (long)br * K_N * K_F;
    float* Cz = P + (long)(chunk * (K_B * K_R) + br) * K_N * K_F;
    float t0 = theta[(l * K_R + r) * K_E + 0];
    float t1 = theta[(l * K_R + r) * K_E + 1];
    float t2 = theta[(l * K_R + r) * K_E + 2];
    int m0 = blockIdx.y * 64;
    int Ks = chunk * (K_N / 2), Ke = Ks + K_N / 2;

    int tid = threadIdx.x;
    int r_ = tid >> 2, q_ = tid & 3;
    int bk = tid >> 4, bc = tid & 15;
    int tx = tid & 15, ty = tid >> 4;

    ull acc[2][4];
#pragma unroll
    for (int i = 0; i < 2; i++)
#pragma unroll
        for (int j = 0; j < 4; j++) acc[i][j] = 0ULL;

    float4 ar, br4;
    {
        long off = (long)(m0 + r_) * K_N + Ks + q_ * 4;
        float4 v0 = *(const float4*)(T0 + off), v1 = *(const float4*)(T1 + off);
        float4 v2 = *(const float4*)(T2 + off), a4 = *(const float4*)(Az + off);
        ar.x = (t0 * v0.x + t1 * v1.x + t2 * v2.x) * a4.x;
        ar.y = (t0 * v0.y + t1 * v1.y + t2 * v2.y) * a4.y;
        ar.z = (t0 * v0.z + t1 * v1.z + t2 * v2.z) * a4.z;
        ar.w = (t0 * v0.w + t1 * v1.w + t2 * v2.w) * a4.w;
        br4 = *(const float4*)&Hz[(long)(Ks + bk) * K_F + bc * 4];
    }
    for (int k0 = Ks; k0 < Ke; k0 += 16) {
        stage_q(As, r_, q_, ar);
        *(float4*)&Bs[bk * SMS + bc * 4] = br4;
        __syncthreads();
        int kn = k0 + 16;
        if (kn < Ke) {
            long off = (long)(m0 + r_) * K_N + kn + q_ * 4;
            float4 v0 = *(const float4*)(T0 + off), v1 = *(const float4*)(T1 + off);
            float4 v2 = *(const float4*)(T2 + off), a4 = *(const float4*)(Az + off);
            ar.x = (t0 * v0.x + t1 * v1.x + t2 * v2.x) * a4.x;
            ar.y = (t0 * v0.y + t1 * v1.y + t2 * v2.y) * a4.y;
            ar.z = (t0 * v0.z + t1 * v1.z + t2 * v2.z) * a4.z;
            ar.w = (t0 * v0.w + t1 * v1.w + t2 * v2.w) * a4.w;
            br4 = *(const float4*)&Hz[(long)(kn + bk) * K_F + bc * 4];
        }
        mma16(As, Bs, tx, ty, acc);
        __syncthreads();
    }
    epi_store(Cz, K_F, m0 + ty * 4, tx * 4, acc, nullptr, 0.f, false);
}

// =============== fused q,k,v projections =====================
// grid (12, 32): which = x>>2, n-tile = x&3. M=2048, K=320.
__global__ void __launch_bounds__(256, 3) k_qkv(
    const float* __restrict__ h,
    const float* __restrict__ qw, const float* __restrict__ kw, const float* __restrict__ vw,
    const float* __restrict__ qb, const float* __restrict__ kb, const float* __restrict__ vb,
    float* __restrict__ q, float* __restrict__ k, float* __restrict__ v)
{
    __shared__ float As[16 * SMS];
    __shared__ float Bs[16 * SMS];
    int which = blockIdx.x >> 2;
    int n0 = (blockIdx.x & 3) * 64;
    int m0 = blockIdx.y * 64;
    const float* W = (which == 0) ? qw : (which == 1) ? kw : vw;
    const float* bb = (which == 0) ? qb : (which == 1) ? kb : vb;
    float* C = (which == 0) ? q : (which == 1) ? k : v;

    ull acc[2][4];
#pragma unroll
    for (int i = 0; i < 2; i++)
#pragma unroll
        for (int j = 0; j < 4; j++) acc[i][j] = 0ULL;
    loop_nt<false>(h + (long)m0 * K_INRET, K_INRET, nullptr,
                   W + (long)n0 * K_INRET, K_INRET, K_INRET, As, Bs, acc);
    int tx = threadIdx.x & 15, ty = threadIdx.x >> 4;
    epi_store(C, K_INTER, m0 + ty * 4, n0 + tx * 4, acc, bb, 0.f, false);
}

// =============== triangular masked scores =====================
// grid (136, 2): linear lower-tri tile index -> (mt, nt). 64x64, K=256.
__global__ void __launch_bounds__(256, 3) k_scores(
    const float* __restrict__ q, const float* __restrict__ k, float* __restrict__ ms)
{
    __shared__ float As[16 * SMS];
    __shared__ float Bs[16 * SMS];
    int i = blockIdx.x;
    int mt = (int)((sqrtf(8.f * i + 1.f) - 1.f) * 0.5f);
    while ((mt + 1) * (mt + 2) / 2 <= i) mt++;
    while (mt * (mt + 1) / 2 > i) mt--;
    int nt = i - mt * (mt + 1) / 2;
    int m0 = mt * 64, n0 = nt * 64;
    int z = blockIdx.y;
    const float* Az = q + (long)z * K_N * K_INTER + (long)m0 * K_INTER;
    const float* Bz = k + (long)z * K_N * K_INTER + (long)n0 * K_INTER;
    float* Cz = ms + (long)z * K_N * K_N;

    ull acc[2][4];
#pragma unroll
    for (int i2 = 0; i2 < 2; i2++)
#pragma unroll
        for (int j = 0; j < 4; j++) acc[i2][j] = 0ULL;
    loop_nt<false>(Az, K_INTER, nullptr, Bz, K_INTER, K_INTER, As, Bs, acc);

    int tx = threadIdx.x & 15, ty = threadIdx.x >> 4;
#pragma unroll
    for (int i2 = 0; i2 < 2; i2++) {
        int r0i = m0 + ty * 4 + 2 * i2;
        float r0[4], r1[4];
#pragma unroll
        for (int j = 0; j < 4; j++) {
            float2 p = unpack2(acc[i2][j]);
            int col = n0 + tx * 4 + j;
            r0[j] = (r0i > col)     ? INV_GAMMA * p.x : 0.f;
            r1[j] = (r0i + 1 > col) ? INV_GAMMA * p.y : 0.f;
        }
        *(float4*)&Cz[(long)r0i * K_N + n0 + tx * 4]       = *(float4*)r0;
        *(float4*)&Cz[(long)(r0i + 1) * K_N + n0 + tx * 4] = *(float4*)r1;
    }
}

// =============== fused eta + ts -> cat =====================
// grid (6, 32): x<4 -> eta tile (Nc=256,K=256, PReLU), x>=4 -> ts tile (Nc=128,K=320).
__global__ void __launch_bounds__(256, 3) k_eta_ts(
    const float* __restrict__ ret, const float* __restrict__ skip,
    const float* __restrict__ rw, const float* __restrict__ rb,
    const float* __restrict__ l1w, const float* __restrict__ l1b,
    const float* __restrict__ a_ret, float* __restrict__ cat)
{
    __shared__ float As[16 * SMS];
    __shared__ float Bs[16 * SMS];
    int x = blockIdx.x;
    int m0 = blockIdx.y * 64;
    bool is_eta = (x < 4);
    int n0 = is_eta ? x * 64 : (x - 4) * 64;
    const float* A = is_eta ? ret : skip;
    int ldA = is_eta ? K_OUTRET : K_HRET;
    const float* B = is_eta ? (rw + (long)n0 * K_INTER) : (l1w + (long)n0 * K_HRET);
    int Kd = is_eta ? K_INTER : K_HRET;
    const float* bb = is_eta ? (rb + n0) : (l1b + n0);
    int cOff = is_eta ? n0 : (K_OUTRET + n0);

    ull acc[2][4];
#pragma unroll
    for (int i = 0; i < 2; i++)
#pragma unroll
        for (int j = 0; j < 4; j++) acc[i][j] = 0ULL;
    loop_nt<false>(A + (long)m0 * ldA, ldA, nullptr, B, Kd, Kd, As, Bs, acc);

    int tx = threadIdx.x & 15, ty = threadIdx.x >> 4;
    float alpha = *a_ret;
#pragma unroll
    for (int i = 0; i < 2; i++) {
        int rr = m0 + ty * 4 + 2 * i;
        float r0[4], r1[4];
#pragma unroll
        for (int j = 0; j < 4; j++) {
            float2 p = unpack2(acc[i][j]);
            float bbv = bb[tx * 4 + j];
            r0[j] = p.x + bbv; r1[j] = p.y + bbv;
            if (is_eta) {
                r0[j] = (r0[j] >= 0.f) ? r0[j] : alpha * r0[j];
                r1[j] = (r1[j] >= 0.f) ? r1[j] : alpha * r1[j];
            }
        }
        *(float4*)&cat[(long)rr * K_CAT + cOff + tx * 4]       = *(float4*)r0;
        *(float4*)&cat[(long)(rr + 1) * K_CAT + cOff + tx * 4] = *(float4*)r1;
    }
}

// ---------------- conv over relations + PReLU ----------------
__global__ void k_conv(const float* __restrict__ diff, const float* __restrict__ cw,
                       const float* __restrict__ cb, const float* __restrict__ a1,
                       int l, float* __restrict__ u) {
    const int PQ = K_N * K_F / 4;
    int i = blockIdx.x * 256 + threadIdx.x;
    if (i >= K_B * K_R * PQ) return;
    int pq = i % PQ; int s = (i / PQ) % K_R; int b = i / (PQ * K_R);
    float bb = cb[l * K_R + s];
    float4 acc = make_float4(bb, bb, bb, bb);
    const float4* d4 = (const float4*)diff;
#pragma unroll
    for (int r2 = 0; r2 < K_R; r2++) {
        float w = cw[(l * K_R + s) * K_R + r2];
        float4 v = d4[(long)(b * K_R + r2) * PQ + pq];
        acc.x += w * v.x; acc.y += w * v.y; acc.z += w * v.z; acc.w += w * v.w;
    }
    float al = a1[l];
    acc.x = (acc.x >= 0.f) ? acc.x : al * acc.x;
    acc.y = (acc.y >= 0.f) ? acc.y : al * acc.y;
    acc.z = (acc.z >= 0.f) ? acc.z : al * acc.z;
    acc.w = (acc.w >= 0.f) ? acc.w : al * acc.w;
    ((float4*)u)[i] = acc;
}

// ---------------- initial skip transpose ----------------
__global__ void k_skip0(const float* __restrict__ x, float* __restrict__ sk) {
    int i = blockIdx.x * 256 + threadIdx.x;
    if (i >= K_B * K_N * K_R * K_F) return;
    int d = i % K_F;
    int r = (i / K_F) % K_R;
    int n = (i / (K_F * K_R)) % K_N;
    int b = i / (K_F * K_R * K_N);
    sk[i] = x[(((long)b * K_R + r) * K_N + n) * K_F + d];
}

// ---------------- final tiny GEMM: out[2048,2] ----------------
__global__ void k_mlp2(const float* __restrict__ m1, const float* __restrict__ w,
                       const float* __restrict__ b, float* __restrict__ out) {
    __shared__ float ws[2 * K_H1];
    int tid = threadIdx.x;
    if (tid < 2 * K_H1) ws[tid] = w[tid];
    __syncthreads();
    int row = blockIdx.x * 256 + tid;
    const float4* mr = (const float4*)(m1 + (long)row * K_H1);
    float s0 = 0.f, s1 = 0.f;
#pragma unroll
    for (int i = 0; i < K_H1 / 4; i++) {
        float4 v = mr[i];
        s0 += v.x * ws[i * 4] + v.y * ws[i * 4 + 1] + v.z * ws[i * 4 + 2] + v.w * ws[i * 4 + 3];
        s1 += v.x * ws[K_H1 + i * 4] + v.y * ws[K_H1 + i * 4 + 1]
            + v.z * ws[K_H1 + i * 4 + 2] + v.w * ws[K_H1 + i * 4 + 3];
    }
    out[(long)row * 2]     = s0 + b[0];
    out[(long)row * 2 + 1] = s1 + b[1];
}

// ---------------- host launcher ----------------
extern "C" void kernel_launch(void* const* d_in, const int* in_sizes, int n_in,
                              void* d_out, int out_size) {
    const float* x      = (const float*)d_in[0];
    const float* a      = (const float*)d_in[1];
    const float* T      = (const float*)d_in[2];
    const float* theta  = (const float*)d_in[3];
    const float* fc_w   = (const float*)d_in[4];
    const float* fc_b   = (const float*)d_in[5];
    const float* conv_w = (const float*)d_in[6];
    const float* conv_b = (const float*)d_in[7];
    const float* a0     = (const float*)d_in[8];
    const float* a1     = (const float*)d_in[9];
    const float* qw = (const float*)d_in[10]; const float* qb = (const float*)d_in[11];
    const float* kw = (const float*)d_in[12]; const float* kb = (const float*)d_in[13];
    const float* vw = (const float*)d_in[14]; const float* vb = (const float*)d_in[15];
    const float* rw = (const float*)d_in[16]; const float* rb = (const float*)d_in[17];
    const float* a_ret = (const float*)d_in[18];
    const float* l1w = (const float*)d_in[19]; const float* l1b = (const float*)d_in[20];
    const float* l2w = (const float*)d_in[21]; const float* l2b = (const float*)d_in[22];
    const float* m1w = (const float*)d_in[23]; const float* m1b = (const float*)d_in[24];
    const float* m2w = (const float*)d_in[25]; const float* m2b = (const float*)d_in[26];
    const float* a_mlp = (const float*)d_in[27];
    float* out = (float*)d_out;

    float *P, *diff, *h, *q, *k, *v, *ms, *ret, *cat, *skA, *skB, *m1;
    cudaGetSymbolAddress((void**)&P, g_featsP);
    cudaGetSymbolAddress((void**)&diff, g_diff);
    cudaGetSymbolAddress((void**)&h, g_h);
    cudaGetSymbolAddress((void**)&q, g_q);
    cudaGetSymbolAddress((void**)&k, g_k);
    cudaGetSymbolAddress((void**)&v, g_v);
    cudaGetSymbolAddress((void**)&ms, g_ms);
    cudaGetSymbolAddress((void**)&ret, g_ret);
    cudaGetSymbolAddress((void**)&cat, g_cat);
    cudaGetSymbolAddress((void**)&skA, g_skipA);
    cudaGetSymbolAddress((void**)&skB, g_skipB);
    cudaGetSymbolAddress((void**)&m1, g_m1);

    const int M2 = K_B * K_N;  // 2048
    const long NF = (long)K_N * K_F;

    { int tot = K_B * K_N * K_R * K_F;
      k_skip0<<<(tot + 255) / 256, 256>>>(x, skA); }

    const float* hc = x;
    float* sin_ = skA;
    float* sout = skB;

    for (int l = 0; l < 2; l++) {
        // diffusion with fused S, split-K x2 -> partials (320 blocks)
        k_feats<<<dim3(1, K_N / 64, K_B * K_R * 2), 256>>>(T, theta, a, hc, P, l);

        // fc + PReLU(a0), partial reduce fused into A staging
        k_gemm64<true, false><<<dim3(1, K_N / 64, K_B * K_R), 256>>>(
            P, P + (long)K_B * K_R * NF,
            fc_w + (long)l * K_R * K_F * K_F, fc_b + (long)l * K_R * K_F, diff,
            K_F, K_F, NF, K_F, (long)K_F * K_F, K_F, K_R, NF, K_F, a0 + l, 0);

        { int tot = K_B * K_R * K_N * K_F / 4;
          k_conv<<<(tot + 255) / 256, 256>>>(diff, conv_w, conv_b, a1, l, h); }
        hc = h;

        // fused q,k,v (384 blocks)
        k_qkv<<<dim3(12, M2 / 64), 256>>>(
            h,
            qw + (long)l * K_INTER * K_INRET, kw + (long)l * K_INTER * K_INRET,
            vw + (long)l * K_INTER * K_INRET,
            qb + (long)l * K_INTER, kb + (long)l * K_INTER, vb + (long)l * K_INTER,
            q, k, v);

        // triangular masked scores (272 blocks)
        k_scores<<<dim3(136, 2), 256>>>(q, k, ms);

        // ret = ms @ v (causal K-limit)
        k_gemm64<false, true><<<dim3(K_OUTRET / 64, K_N / 64, K_B), 256>>>(
            ms, nullptr, v, nullptr, ret,
            K_OUTRET, K_N, (long)K_N * K_N, K_N,
            (long)K_N * K_INTER, K_INTER, 1, (long)K_N * K_OUTRET, K_OUTRET,
            nullptr, 1);

        // fused eta (PReLU) + ts -> cat (192 blocks)
        k_eta_ts<<<dim3(6, M2 / 64), 256>>>(
            ret, sin_,
            rw + (long)l * K_OUTRET * K_INTER, rb + (long)l * K_OUTRET,
            l1w + (long)l * K_H1 * K_HRET, l1b + (long)l * K_H1,
            a_ret + l, cat);

        // skip' = cat @ l2^T + l2_b (160 blocks)
        k_gemm64<false, false><<<dim3(K_HRET / 64, M2 / 64, 1), 256>>>(
            cat, nullptr, l2w + (long)l * K_HRET * K_CAT, l2b + (long)l * K_HRET, sout,
            K_HRET, K_CAT, 0, K_CAT, 0, K_CAT, 1, 0, K_HRET, nullptr, 0);

        float* t0 = sin_; sin_ = sout; sout = t0;
    }

    // final MLP
    k_gemm64<false, false><<<dim3(K_H1 / 64, M2 / 64, 1), 256>>>(
        sin_, nullptr, m1w, m1b, m1,
        K_H1, K_HRET, 0, K_HRET, 0, K_HRET, 1, 0, K_H1, a_mlp, 0);
    k_mlp2<<<M2 / 256, 256>>>(m1, m2w, m2b, out);
}